// round 4
// baseline (speedup 1.0000x reference)
#include <cuda_runtime.h>

#define L_SEQ 512
#define T_TAGS 64
#define WARPS 8     // 1 chain per warp

#define FMA2(d, a, b) asm("fma.rn.f32x2 %0, %1, %2, %0;" : "+l"(d) : "l"(a), "l"(b))
#define ADD2(d, a)    asm("add.rn.f32x2 %0, %0, %1;"      : "+l"(d) : "l"(a))

__device__ __forceinline__ unsigned long long pack2(float x, float y) {
    unsigned long long r;
    asm("mov.b64 %0, {%1, %2};" : "=l"(r) : "f"(x), "f"(y));
    return r;
}

__global__ __launch_bounds__(256, 1)
void crf_kernel(const float* __restrict__ logits,
                const unsigned int* __restrict__ tagw,
                const int* __restrict__ mask,
                const float* __restrict__ trans,
                float* __restrict__ out)
{
    // dup-pair p buffer, double-buffered per warp: 64 u64 pairs = 128 floats + pad
    __shared__ float pbuf[2][WARPS][132];

    const int tid  = threadIdx.x;
    const int w    = tid >> 5;
    const int lane = tid & 31;
    const int j0   = lane << 1;                 // this lane owns tags j0, j0+1
    const int b    = blockIdx.x * WARPS + w;

    // ---- tag dtype detection (int64 LE => odd 32-bit words all zero) ----
    unsigned oddacc = 0;
    #pragma unroll
    for (int k = 0; k < 4; ++k) oddacc |= tagw[2 * (lane + 32 * k) + 1];
    const int is64 = __all_sync(0xffffffffu, oddacc == 0) ? 1 : 0;

    // ---- full register cache of exp(trans): rows 0..63, cols j0..j0+1 ----
    unsigned long long ec[64];
    #pragma unroll
    for (int i = 0; i < 64; ++i) {
        float2 t = *(const float2*)&trans[i * 64 + j0];
        ec[i] = pack2(__expf(t.x), __expf(t.y));
    }

    const float* lg = logits + (size_t)b * (L_SEQ * T_TAGS);
    const int mbase = b * L_SEQ;

    // ---- l = 0 ----
    float2 a0 = *(const float2*)(lg + j0);
    float al0 = a0.x, al1 = a0.y;

    int t0 = (int)tagw[is64 ? (mbase << 1) : mbase];
    float gold = 0.f;
    {
        float m0 = (float)mask[mbase];
        if ((t0 >> 1) == lane) gold = ((t0 & 1) ? a0.y : a0.x) * m0;
    }
    int tprev = t0;

    // shift for step 1 (any group-uniform value is exact; use alpha[0])
    float shift = __shfl_sync(0xffffffffu, al0, 0);

    // current-step (l = 1) operands, prefetched
    float2 cem = *(const float2*)(lg + T_TAGS + j0);
    int cm = mask[mbase + 1];
    int ct = (int)tagw[is64 ? ((mbase + 1) << 1) : (mbase + 1)];

    for (int l = 1; l < L_SEQ; ++l) {
        const int buf = l & 1;

        // depth-1 prefetch (clamped) + gold transition load, issued early
        const int lp = (l + 1 < L_SEQ) ? (l + 1) : (L_SEQ - 1);
        float2 nem = *(const float2*)(lg + lp * T_TAGS + j0);
        int nm = mask[mbase + lp];
        int nt = (int)tagw[is64 ? ((mbase + lp) << 1) : (mbase + lp)];
        float tv = __ldg(&trans[tprev * 64 + ct]);

        // ---- p = exp(alpha - shift), stored as duplicated pairs ----
        float p0 = __expf(al0 - shift);
        float p1 = __expf(al1 - shift);
        float* pb = &pbuf[buf][w][0];
        *(float4*)(pb + 4 * lane) = make_float4(p0, p0, p1, p1);
        __syncwarp();

        // ---- s[j] = sum_i p[i]*expT[i][j]; 8-deep pipelined LDS.128 ----
        const ulonglong2* pq = (const ulonglong2*)pb;   // 32 entries, 2 rows each
        unsigned long long sA = 0ull, sB = 0ull, sC = 0ull, sD = 0ull;
        ulonglong2 q[8];
        #pragma unroll
        for (int g = 0; g < 8; ++g) q[g] = pq[g];
        #pragma unroll
        for (int g = 0; g < 32; ++g) {
            ulonglong2 cur = q[g & 7];
            if (g < 24) q[g & 7] = pq[g + 8];
            if (g & 1) {
                FMA2(sC, cur.x, ec[2 * g]);
                FMA2(sD, cur.y, ec[2 * g + 1]);
            } else {
                FMA2(sA, cur.x, ec[2 * g]);
                FMA2(sB, cur.y, ec[2 * g + 1]);
            }
        }
        ADD2(sA, sB);
        ADD2(sC, sD);
        ADD2(sA, sC);

        float s0, s1;
        asm("mov.b64 {%0, %1}, %2;" : "=f"(s0), "=f"(s1) : "l"(sA));

        float n0 = shift + __logf(s0) + cem.x;
        float n1 = shift + __logf(s1) + cem.y;

        bool keep = cm > 0;
        al0 = keep ? n0 : al0;
        al1 = keep ? n1 : al1;

        // shift for NEXT step — shfl latency hidden behind loop tail
        shift = __shfl_sync(0xffffffffu, al0, 0);

        // ---- gold score (off critical path) ----
        float lm = (float)cm;
        if ((ct >> 1) == lane) gold += ((ct & 1) ? cem.y : cem.x) * lm;
        if (lane == 0) gold += tv * lm;
        tprev = ct;

        cem = nem; cm = nm; ct = nt;
    }

    // ---- final logsumexp over the 64 alphas (2 per lane) ----
    float mx = fmaxf(al0, al1);
    #pragma unroll
    for (int d = 1; d < 32; d <<= 1)
        mx = fmaxf(mx, __shfl_xor_sync(0xffffffffu, mx, d));

    float s = __expf(al0 - mx) + __expf(al1 - mx);
    #pragma unroll
    for (int d = 1; d < 32; d <<= 1)
        s += __shfl_xor_sync(0xffffffffu, s, d);

    #pragma unroll
    for (int d = 1; d < 32; d <<= 1)
        gold += __shfl_xor_sync(0xffffffffu, gold, d);

    if (lane == 0) out[b] = (mx + __logf(s)) - gold;
}

extern "C" void kernel_launch(void* const* d_in, const int* in_sizes, int n_in,
                              void* d_out, int out_size)
{
    const float*        logits = (const float*)d_in[0];
    const unsigned int* tagw   = (const unsigned int*)d_in[1];
    const int*          mask   = (const int*)d_in[2];
    const float*        trans  = (const float*)d_in[3];
    float*              out    = (float*)d_out;

    crf_kernel<<<128, 256>>>(logits, tagw, mask, trans, out);
}